// round 1
// baseline (speedup 1.0000x reference)
#include <cuda_runtime.h>
#include <math_constants.h>

// ---------------------------------------------------------------------------
// Net_40312563041045: 4-layer max-tempered MLP
//   layer(x; W, b) = 0.8 * (x @ W^T) + 0.2 * max_k(W[o,k] * x[b,k]) + b
// Shapes: x (1024,256); W1 (512,256); W2,W3 (512,512); W4 (1,512); out (1024,)
// All fp32. Scalar-pipe bound (max term forbids tensor cores).
// Uses packed f32x2 mul/add (inline PTX) to halve fma-pipe instruction count.
// ---------------------------------------------------------------------------

#define B_TOTAL 1024
#define WIDTH   512

// Inter-layer activation scratch (device globals: allocation-free).
__device__ float g_h1[B_TOTAL * WIDTH];
__device__ float g_h2[B_TOTAL * WIDTH];
__device__ float g_h3[B_TOTAL * WIDTH];

// ---- packed f32x2 helpers (sm_103a) ---------------------------------------
__device__ __forceinline__ unsigned long long f32x2_mul(unsigned long long a,
                                                        unsigned long long b) {
    unsigned long long r;
    asm("mul.rn.f32x2 %0, %1, %2;" : "=l"(r) : "l"(a), "l"(b));
    return r;
}
__device__ __forceinline__ unsigned long long f32x2_add(unsigned long long a,
                                                        unsigned long long b) {
    unsigned long long r;
    asm("add.rn.f32x2 %0, %1, %2;" : "=l"(r) : "l"(a), "l"(b));
    return r;
}
__device__ __forceinline__ void f32x2_unpack(float& lo, float& hi,
                                             unsigned long long v) {
    asm("mov.b64 {%0, %1}, %2;" : "=f"(lo), "=f"(hi) : "l"(v));
}

// ---------------------------------------------------------------------------
// Main layer kernel: Y[b,o] = 0.8*sum_k W[o,k]*X[b,k] + 0.2*max_k(...) + bias[o]
// Tile: 64 (batch) x 64 (out) per 256-thread block. BK=32 smem staging.
// Thread tile 4x4, strided (o = tx + 16*j, b = ty + 16*i).
// smem stride 34 floats: conflict-free LDS.64 for both x (broadcast) and w.
// ---------------------------------------------------------------------------
template <int K>
__global__ __launch_bounds__(256, 2)
void layer_kernel(const float* __restrict__ X,   // (B_TOTAL, K)
                  const float* __restrict__ W,   // (512, K)
                  const float* __restrict__ bias,// (512,)
                  float* __restrict__ Y)         // (B_TOTAL, 512)
{
    constexpr int BK = 32;
    constexpr int STRIDE = 34;  // pad: even (8B-aligned LDS.64), 2l mod 32 bank map

    __shared__ float xs[64][STRIDE];
    __shared__ float ws[64][STRIDE];

    const int tid = threadIdx.x;
    const int tx = tid & 15;   // out groups
    const int ty = tid >> 4;   // batch groups

    const int o0 = blockIdx.x * 64;
    const int b0 = blockIdx.y * 64;

    // load indices: each thread loads 2 float4 for x and 2 for w per k-tile
    const int lrow = tid >> 3;        // 0..31
    const int lcol = (tid & 7) * 4;   // 0,4,...,28

    unsigned long long acc[4][4];
    float mlo[4][4], mhi[4][4];
#pragma unroll
    for (int i = 0; i < 4; i++)
#pragma unroll
        for (int j = 0; j < 4; j++) {
            acc[i][j] = 0ull;
            mlo[i][j] = -CUDART_INF_F;
            mhi[i][j] = -CUDART_INF_F;
        }

    for (int kt = 0; kt < K; kt += BK) {
#pragma unroll
        for (int r = 0; r < 2; r++) {
            const int row = lrow + r * 32;
            float4 xv = *reinterpret_cast<const float4*>(
                &X[(size_t)(b0 + row) * K + kt + lcol]);
            float4 wv = *reinterpret_cast<const float4*>(
                &W[(size_t)(o0 + row) * K + kt + lcol]);
            *reinterpret_cast<float2*>(&xs[row][lcol])     = make_float2(xv.x, xv.y);
            *reinterpret_cast<float2*>(&xs[row][lcol + 2]) = make_float2(xv.z, xv.w);
            *reinterpret_cast<float2*>(&ws[row][lcol])     = make_float2(wv.x, wv.y);
            *reinterpret_cast<float2*>(&ws[row][lcol + 2]) = make_float2(wv.z, wv.w);
        }
        __syncthreads();

#pragma unroll 4
        for (int kk = 0; kk < BK; kk += 2) {
            unsigned long long xv[4], wv[4];
#pragma unroll
            for (int i = 0; i < 4; i++)
                xv[i] = *reinterpret_cast<const unsigned long long*>(
                    &xs[ty + 16 * i][kk]);
#pragma unroll
            for (int j = 0; j < 4; j++)
                wv[j] = *reinterpret_cast<const unsigned long long*>(
                    &ws[tx + 16 * j][kk]);
#pragma unroll
            for (int i = 0; i < 4; i++) {
#pragma unroll
                for (int j = 0; j < 4; j++) {
                    unsigned long long p = f32x2_mul(xv[i], wv[j]);
                    acc[i][j] = f32x2_add(acc[i][j], p);
                    float plo, phi;
                    f32x2_unpack(plo, phi, p);  // free (register pair aliasing)
                    mlo[i][j] = fmaxf(mlo[i][j], plo);
                    mhi[i][j] = fmaxf(mhi[i][j], phi);
                }
            }
        }
        __syncthreads();
    }

#pragma unroll
    for (int j = 0; j < 4; j++) {
        const int o = o0 + tx + 16 * j;
        const float bo = bias[o];
#pragma unroll
        for (int i = 0; i < 4; i++) {
            const int b = b0 + ty + 16 * i;
            float slo, shi;
            f32x2_unpack(slo, shi, acc[i][j]);
            const float sum = slo + shi;
            const float mx = fmaxf(mlo[i][j], mhi[i][j]);
            Y[(size_t)b * WIDTH + o] = 0.8f * sum + 0.2f * mx + bo;
        }
    }
}

// ---------------------------------------------------------------------------
// Final layer: O = 1. One warp per batch row, shuffle-reduce sum and max.
// ---------------------------------------------------------------------------
__global__ __launch_bounds__(256)
void layer4_kernel(const float* __restrict__ H,   // (1024, 512)
                   const float* __restrict__ W4,  // (512,)
                   const float* __restrict__ b4,  // (1,)
                   float* __restrict__ out)       // (1024,)
{
    const int warp = (blockIdx.x * blockDim.x + threadIdx.x) >> 5;
    const int lane = threadIdx.x & 31;
    if (warp >= B_TOTAL) return;

    const float* h = H + (size_t)warp * WIDTH;
    float s = 0.0f, m = -CUDART_INF_F;
#pragma unroll
    for (int k = lane; k < WIDTH; k += 32) {
        const float p = W4[k] * h[k];
        s += p;
        m = fmaxf(m, p);
    }
#pragma unroll
    for (int o = 16; o > 0; o >>= 1) {
        s += __shfl_xor_sync(0xffffffffu, s, o);
        m = fmaxf(m, __shfl_xor_sync(0xffffffffu, m, o));
    }
    if (lane == 0) out[warp] = 0.8f * s + 0.2f * m + b4[0];
}

// ---------------------------------------------------------------------------
extern "C" void kernel_launch(void* const* d_in, const int* in_sizes, int n_in,
                              void* d_out, int out_size)
{
    const float* x  = (const float*)d_in[0];
    const float* W1 = (const float*)d_in[1];
    const float* b1 = (const float*)d_in[2];
    const float* W2 = (const float*)d_in[3];
    const float* b2 = (const float*)d_in[4];
    const float* W3 = (const float*)d_in[5];
    const float* b3 = (const float*)d_in[6];
    const float* W4 = (const float*)d_in[7];
    const float* b4 = (const float*)d_in[8];
    float* out = (float*)d_out;

    float *h1, *h2, *h3;
    cudaGetSymbolAddress((void**)&h1, g_h1);
    cudaGetSymbolAddress((void**)&h2, g_h2);
    cudaGetSymbolAddress((void**)&h3, g_h3);

    const dim3 grid(WIDTH / 64, B_TOTAL / 64);  // (8, 16)
    layer_kernel<256><<<grid, 256>>>(x,  W1, b1, h1);
    layer_kernel<512><<<grid, 256>>>(h1, W2, b2, h2);
    layer_kernel<512><<<grid, 256>>>(h2, W3, b3, h3);
    layer4_kernel<<<(B_TOTAL * 32) / 256, 256>>>(h3, W4, b4, out);
}

// round 6
// speedup vs baseline: 1.0269x; 1.0269x over previous
#include <cuda_runtime.h>
#include <math_constants.h>
#include <cstdint>

// ---------------------------------------------------------------------------
// Net_40312563041045: 4-layer max-tempered MLP
//   layer(x; W, b) = 0.8 * (x @ W^T) + 0.2 * max_k(W[o,k] * x[b,k]) + b
// Shapes: x (1024,256); W1 (512,256); W2,W3 (512,512); W4 (1,512); out (1024,)
// Issue-port bound scalar work (max term forbids tensor cores).
// v2: cp.async double-buffered pipeline, 256-block grid, fused f32x2 MAC asm.
// ---------------------------------------------------------------------------

#define B_TOTAL 1024
#define WIDTH   512

__device__ float g_h1[B_TOTAL * WIDTH];
__device__ float g_h2[B_TOTAL * WIDTH];
__device__ float g_h3[B_TOTAL * WIDTH];

// Fused packed MAC: acc(f32x2) += x*w ; mlo/mhi = max with product halves.
// Single asm block so ptxas can alias the mov.b64 unpack to the product pair.
__device__ __forceinline__ void mac2(unsigned long long x, unsigned long long w,
                                     unsigned long long& acc, float& mlo, float& mhi) {
    asm("{\n\t"
        ".reg .b64 p;\n\t"
        ".reg .f32 plo, phi;\n\t"
        "mul.rn.f32x2 p, %3, %4;\n\t"
        "add.rn.f32x2 %0, %0, p;\n\t"
        "mov.b64 {plo, phi}, p;\n\t"
        "max.f32 %1, %1, plo;\n\t"
        "max.f32 %2, %2, phi;\n\t"
        "}\n"
        : "+l"(acc), "+f"(mlo), "+f"(mhi)
        : "l"(x), "l"(w));
}

__device__ __forceinline__ void cp_async8(uint32_t smem_addr, const float* gptr) {
    asm volatile("cp.async.ca.shared.global [%0], [%1], 8;\n"
                 :: "r"(smem_addr), "l"(gptr));
}
__device__ __forceinline__ void cp_commit() {
    asm volatile("cp.async.commit_group;\n" ::: "memory");
}
__device__ __forceinline__ void cp_wait0() {
    asm volatile("cp.async.wait_group 0;\n" ::: "memory");
}

// ---------------------------------------------------------------------------
// Main layer: tile = 64 out x 32 batch per 256-thread block. Thread tile 4x2.
// BK=32 double-buffered smem (stride 34 floats: conflict-free LDS.64 for the
// w reads (bank = 2*tx + kk, all distinct over tx=0..15) and broadcast x reads).
// grid = (512/64, 1024/32) = (8, 32) = 256 blocks -> 2 CTAs on most SMs.
// ---------------------------------------------------------------------------
template <int K>
__global__ __launch_bounds__(256, 2)
void layer_kernel(const float* __restrict__ X,    // (1024, K)
                  const float* __restrict__ W,    // (512, K)
                  const float* __restrict__ bias, // (512,)
                  float* __restrict__ Y)          // (1024, 512)
{
    constexpr int BK = 32;
    constexpr int TILES = K / BK;
    constexpr int S = 34;               // smem row stride in floats

    __shared__ float ws[2][64 * S];
    __shared__ float xs[2][32 * S];

    const int tid = threadIdx.x;
    const int tx = tid & 15;            // out lane   (o = o0 + tx + 16j)
    const int ty = tid >> 4;            // batch lane (b = b0 + ty + 16i)
    const int o0 = blockIdx.x * 64;
    const int b0 = blockIdx.y * 32;

    // staging: 8-byte chunks, 16 chunks per 32-float row
    const int crow = tid >> 4;          // 0..15
    const int ccol = (tid & 15) * 2;    // 0..30

    const uint32_t ws_base = (uint32_t)__cvta_generic_to_shared(&ws[0][0]);
    const uint32_t xs_base = (uint32_t)__cvta_generic_to_shared(&xs[0][0]);
    constexpr uint32_t WS_BUF = 64 * S * 4;   // bytes per ws buffer
    constexpr uint32_t XS_BUF = 32 * S * 4;

    const float* Xg = X + (size_t)b0 * K + crow * K + ccol;
    const float* Wg = W + (size_t)o0 * K + crow * K + ccol;

    auto load_tile = [&](int kt, int bf) {
        const uint32_t wb = ws_base + bf * WS_BUF;
        const uint32_t xb = xs_base + bf * XS_BUF;
#pragma unroll
        for (int r = 0; r < 4; r++)     // 64 w rows
            cp_async8(wb + ((crow + 16 * r) * S + ccol) * 4,
                      Wg + (size_t)(16 * r) * K + kt);
#pragma unroll
        for (int r = 0; r < 2; r++)     // 32 x rows
            cp_async8(xb + ((crow + 16 * r) * S + ccol) * 4,
                      Xg + (size_t)(16 * r) * K + kt);
        cp_commit();
    };

    unsigned long long acc[2][4];
    float mlo[2][4], mhi[2][4];
#pragma unroll
    for (int i = 0; i < 2; i++)
#pragma unroll
        for (int j = 0; j < 4; j++) {
            acc[i][j] = 0ull;
            mlo[i][j] = -CUDART_INF_F;
            mhi[i][j] = -CUDART_INF_F;
        }

    load_tile(0, 0);

    for (int t = 0; t < TILES; t++) {
        cp_wait0();
        __syncthreads();
        if (t + 1 < TILES) load_tile((t + 1) * BK, (t + 1) & 1);

        const float* wsb = &ws[t & 1][0];
        const float* xsb = &xs[t & 1][0];

#pragma unroll 4
        for (int kk = 0; kk < BK; kk += 2) {
            unsigned long long xv[2], wv[4];
#pragma unroll
            for (int i = 0; i < 2; i++)
                xv[i] = *reinterpret_cast<const unsigned long long*>(
                    &xsb[(ty + 16 * i) * S + kk]);
#pragma unroll
            for (int j = 0; j < 4; j++)
                wv[j] = *reinterpret_cast<const unsigned long long*>(
                    &wsb[(tx + 16 * j) * S + kk]);
#pragma unroll
            for (int i = 0; i < 2; i++)
#pragma unroll
                for (int j = 0; j < 4; j++)
                    mac2(xv[i], wv[j], acc[i][j], mlo[i][j], mhi[i][j]);
        }
        __syncthreads();
    }

#pragma unroll
    for (int j = 0; j < 4; j++) {
        const int o = o0 + tx + 16 * j;
        const float bo = bias[o];
#pragma unroll
        for (int i = 0; i < 2; i++) {
            const int b = b0 + ty + 16 * i;
            float slo, shi;
            asm("mov.b64 {%0, %1}, %2;" : "=f"(slo), "=f"(shi) : "l"(acc[i][j]));
            const float sum = slo + shi;
            const float mx = fmaxf(mlo[i][j], mhi[i][j]);
            Y[(size_t)b * WIDTH + o] = 0.8f * sum + 0.2f * mx + bo;
        }
    }
}

// ---------------------------------------------------------------------------
// Final layer (O=1): one warp per batch row, 2x float4 per lane per iter.
// ---------------------------------------------------------------------------
__global__ __launch_bounds__(256)
void layer4_kernel(const float* __restrict__ H,   // (1024, 512)
                   const float* __restrict__ W4,  // (512,)
                   const float* __restrict__ b4,  // (1,)
                   float* __restrict__ out)       // (1024,)
{
    const int row = (blockIdx.x * blockDim.x + threadIdx.x) >> 5;
    const int lane = threadIdx.x & 31;
    if (row >= B_TOTAL) return;

    const float4* h = reinterpret_cast<const float4*>(H + (size_t)row * WIDTH);
    const float4* w = reinterpret_cast<const float4*>(W4);

    float s = 0.0f, m = -CUDART_INF_F;
    // 128 float4 per row; batch all 4 loads per lane up front (MLP=8 w/ weights)
    float4 hv[4], wv[4];
#pragma unroll
    for (int it = 0; it < 4; it++) {
        hv[it] = h[lane + 32 * it];
        wv[it] = w[lane + 32 * it];
    }
#pragma unroll
    for (int it = 0; it < 4; it++) {
        const float p0 = hv[it].x * wv[it].x, p1 = hv[it].y * wv[it].y;
        const float p2 = hv[it].z * wv[it].z, p3 = hv[it].w * wv[it].w;
        s += (p0 + p1) + (p2 + p3);
        m = fmaxf(m, fmaxf(fmaxf(p0, p1), fmaxf(p2, p3)));
    }
#pragma unroll
    for (int o = 16; o > 0; o >>= 1) {
        s += __shfl_xor_sync(0xffffffffu, s, o);
        m = fmaxf(m, __shfl_xor_sync(0xffffffffu, m, o));
    }
    if (lane == 0) out[row] = 0.8f * s + 0.2f * m + b4[0];
}

// ---------------------------------------------------------------------------
extern "C" void kernel_launch(void* const* d_in, const int* in_sizes, int n_in,
                              void* d_out, int out_size)
{
    const float* x  = (const float*)d_in[0];
    const float* W1 = (const float*)d_in[1];
    const float* b1 = (const float*)d_in[2];
    const float* W2 = (const float*)d_in[3];
    const float* b2 = (const float*)d_in[4];
    const float* W3 = (const float*)d_in[5];
    const float* b3 = (const float*)d_in[6];
    const float* W4 = (const float*)d_in[7];
    const float* b4 = (const float*)d_in[8];
    float* out = (float*)d_out;

    float *h1, *h2, *h3;
    cudaGetSymbolAddress((void**)&h1, g_h1);
    cudaGetSymbolAddress((void**)&h2, g_h2);
    cudaGetSymbolAddress((void**)&h3, g_h3);

    const dim3 grid(WIDTH / 64, B_TOTAL / 32);  // (8, 32) = 256 blocks
    layer_kernel<256><<<grid, 256>>>(x,  W1, b1, h1);
    layer_kernel<512><<<grid, 256>>>(h1, W2, b2, h2);
    layer_kernel<512><<<grid, 256>>>(h2, W3, b3, h3);
    layer4_kernel<<<(B_TOTAL * 32) / 256, 256>>>(h3, W4, b4, out);
}